// round 1
// baseline (speedup 1.0000x reference)
#include <cuda_runtime.h>
#include <math.h>

#define EDGE_TPB 128
#define UPD_TPB  128

// Aggregation scratch: [N, 16 + 24] floats (N = 50000 for this problem)
__device__ float g_agg[50048 * 40];

// ---------------- cooperative scaled weight load ----------------
__device__ __forceinline__ void load_scaled(float* __restrict__ dst,
                                            const float* __restrict__ src,
                                            int n4, float sc, int tid, int nt) {
    for (int t = tid; t < n4; t += nt) {
        float4 v = reinterpret_cast<const float4*>(src)[t];
        v.x *= sc; v.y *= sc; v.z *= sc; v.w *= sc;
        reinterpret_cast<float4*>(dst)[t] = v;
    }
}

// ---------------- generic l<=1 FullyConnectedTensorProduct ----------------
// Normalization constants are pre-folded into the SMEM weights.
// so[k]    += sum_ij s1_i s2_j Wss[ijk]  +  sum_ij (v1_i . v2_j) Wvvs[ijk]
// vo[k][c] += sum_ij s1_i v2_jc Wsv[ijk] + sum_ij v1_ic s2_j Wvs[ijk]
//           + sum_ij (v1_i x v2_j)_c Wvvv[ijk]
template<int M1S, int M2S, int M1V, int M2V, int KS, int KV>
__device__ __forceinline__ void fctp(
    const float* s1, const float* v1, const float* s2, const float* v2,
    const float* __restrict__ wss, const float* __restrict__ wsv,
    const float* __restrict__ wvs, const float* __restrict__ wvvs,
    const float* __restrict__ wvvv,
    float (&so)[KS], float (&vo)[KV * 3])
{
#pragma unroll
    for (int k = 0; k < KS; k++) so[k] = 0.f;
#pragma unroll
    for (int k = 0; k < KV * 3; k++) vo[k] = 0.f;

    // 0 x 0 -> 0
#pragma unroll 1
    for (int i = 0; i < M1S; i++) {
        float a = s1[i];
#pragma unroll 1
        for (int j = 0; j < M2S; j++) {
            float p = a * s2[j];
            const float4* w = reinterpret_cast<const float4*>(wss + (i * M2S + j) * KS);
#pragma unroll
            for (int k = 0; k < KS / 4; k++) {
                float4 ww = w[k];
                so[4 * k + 0] += p * ww.x; so[4 * k + 1] += p * ww.y;
                so[4 * k + 2] += p * ww.z; so[4 * k + 3] += p * ww.w;
            }
        }
    }
    // 1 x 1 -> 0 (dot)
#pragma unroll 1
    for (int i = 0; i < M1V; i++) {
        float ax = v1[3 * i + 0], ay = v1[3 * i + 1], az = v1[3 * i + 2];
#pragma unroll 1
        for (int j = 0; j < M2V; j++) {
            float d = ax * v2[3 * j + 0] + ay * v2[3 * j + 1] + az * v2[3 * j + 2];
            const float4* w = reinterpret_cast<const float4*>(wvvs + (i * M2V + j) * KS);
#pragma unroll
            for (int k = 0; k < KS / 4; k++) {
                float4 ww = w[k];
                so[4 * k + 0] += d * ww.x; so[4 * k + 1] += d * ww.y;
                so[4 * k + 2] += d * ww.z; so[4 * k + 3] += d * ww.w;
            }
        }
    }
    // 0 x 1 -> 1 : contract s1 with W over i first (per j)
#pragma unroll 1
    for (int j = 0; j < M2V; j++) {
        float A[KV];
#pragma unroll
        for (int k = 0; k < KV; k++) A[k] = 0.f;
#pragma unroll 1
        for (int i = 0; i < M1S; i++) {
            float a = s1[i];
            const float4* w = reinterpret_cast<const float4*>(wsv + (i * M2V + j) * KV);
#pragma unroll
            for (int k = 0; k < KV / 4; k++) {
                float4 ww = w[k];
                A[4 * k + 0] += a * ww.x; A[4 * k + 1] += a * ww.y;
                A[4 * k + 2] += a * ww.z; A[4 * k + 3] += a * ww.w;
            }
        }
        float bx = v2[3 * j + 0], by = v2[3 * j + 1], bz = v2[3 * j + 2];
#pragma unroll
        for (int k = 0; k < KV; k++) {
            vo[3 * k + 0] += A[k] * bx; vo[3 * k + 1] += A[k] * by; vo[3 * k + 2] += A[k] * bz;
        }
    }
    // 1 x 0 -> 1 : contract s2 with W over j first (per i)
#pragma unroll 1
    for (int i = 0; i < M1V; i++) {
        float A[KV];
#pragma unroll
        for (int k = 0; k < KV; k++) A[k] = 0.f;
#pragma unroll 1
        for (int j = 0; j < M2S; j++) {
            float b = s2[j];
            const float4* w = reinterpret_cast<const float4*>(wvs + (i * M2S + j) * KV);
#pragma unroll
            for (int k = 0; k < KV / 4; k++) {
                float4 ww = w[k];
                A[4 * k + 0] += b * ww.x; A[4 * k + 1] += b * ww.y;
                A[4 * k + 2] += b * ww.z; A[4 * k + 3] += b * ww.w;
            }
        }
        float ax = v1[3 * i + 0], ay = v1[3 * i + 1], az = v1[3 * i + 2];
#pragma unroll
        for (int k = 0; k < KV; k++) {
            vo[3 * k + 0] += A[k] * ax; vo[3 * k + 1] += A[k] * ay; vo[3 * k + 2] += A[k] * az;
        }
    }
    // 1 x 1 -> 1 (cross)
#pragma unroll 1
    for (int i = 0; i < M1V; i++) {
        float ax = v1[3 * i + 0], ay = v1[3 * i + 1], az = v1[3 * i + 2];
#pragma unroll 1
        for (int j = 0; j < M2V; j++) {
            float bx = v2[3 * j + 0], by = v2[3 * j + 1], bz = v2[3 * j + 2];
            float cx = ay * bz - az * by;
            float cy = az * bx - ax * bz;
            float cz = ax * by - ay * bx;
            const float4* w = reinterpret_cast<const float4*>(wvvv + (i * M2V + j) * KV);
#pragma unroll
            for (int k = 0; k < KV / 4; k++) {
                float4 ww = w[k];
                vo[12 * k + 0] += cx * ww.x; vo[12 * k + 1]  += cy * ww.x; vo[12 * k + 2]  += cz * ww.x;
                vo[12 * k + 3] += cx * ww.y; vo[12 * k + 4]  += cy * ww.y; vo[12 * k + 5]  += cz * ww.y;
                vo[12 * k + 6] += cx * ww.z; vo[12 * k + 7]  += cy * ww.z; vo[12 * k + 8]  += cz * ww.z;
                vo[12 * k + 9] += cx * ww.w; vo[12 * k + 10] += cy * ww.w; vo[12 * k + 11] += cz * ww.w;
            }
        }
    }
}

// ---------------- gate (silu + sigmoid-gated vectors) + per-l linear ----------------
template<int KS, int KV, int OSC, int OVC>
__device__ __forceinline__ void gate_lin(
    const float (&hs)[KS], const float (&hv)[KV * 3],
    const float* __restrict__ ls, const float* __restrict__ lv,
    float (&os)[OSC], float (&ov)[OVC * 3])
{
    float gsl[KS - KV];
#pragma unroll
    for (int t = 0; t < KS - KV; t++) {
        float x = hs[t];
        gsl[t] = x * __fdividef(1.f, 1.f + __expf(-x));
    }
    float gvl[KV * 3];
#pragma unroll
    for (int t = 0; t < KV; t++) {
        float g = __fdividef(1.f, 1.f + __expf(-hs[(KS - KV) + t]));
        gvl[3 * t + 0] = hv[3 * t + 0] * g;
        gvl[3 * t + 1] = hv[3 * t + 1] * g;
        gvl[3 * t + 2] = hv[3 * t + 2] * g;
    }
#pragma unroll
    for (int k = 0; k < OSC; k++) os[k] = 0.f;
#pragma unroll
    for (int k = 0; k < OVC * 3; k++) ov[k] = 0.f;
#pragma unroll 1
    for (int i = 0; i < KS - KV; i++) {
        float a = gsl[i];
        const float4* w = reinterpret_cast<const float4*>(ls + i * OSC);
#pragma unroll
        for (int k = 0; k < OSC / 4; k++) {
            float4 ww = w[k];
            os[4 * k + 0] += a * ww.x; os[4 * k + 1] += a * ww.y;
            os[4 * k + 2] += a * ww.z; os[4 * k + 3] += a * ww.w;
        }
    }
#pragma unroll 1
    for (int i = 0; i < KV; i++) {
        float ax = gvl[3 * i + 0], ay = gvl[3 * i + 1], az = gvl[3 * i + 2];
        const float4* w = reinterpret_cast<const float4*>(lv + i * OVC);
#pragma unroll
        for (int k = 0; k < OVC / 4; k++) {
            float4 ww = w[k];
            ov[12 * k + 0] += ax * ww.x; ov[12 * k + 1]  += ay * ww.x; ov[12 * k + 2]  += az * ww.x;
            ov[12 * k + 3] += ax * ww.y; ov[12 * k + 4]  += ay * ww.y; ov[12 * k + 5]  += az * ww.y;
            ov[12 * k + 6] += ax * ww.z; ov[12 * k + 7]  += ay * ww.z; ov[12 * k + 8]  += az * ww.z;
            ov[12 * k + 9] += ax * ww.w; ov[12 * k + 10] += ay * ww.w; ov[12 * k + 11] += az * ww.w;
        }
    }
}

// ---------------- kernels ----------------
__global__ void zero_agg_kernel(int n) {
    int i = blockIdx.x * blockDim.x + threadIdx.x;
    if (i < n) g_agg[i] = 0.f;
}

__global__ __launch_bounds__(EDGE_TPB) void edge_kernel(
    const float* __restrict__ node_s, const float* __restrict__ node_v,
    const float* __restrict__ edge_s, const float* __restrict__ edge_v,
    const int* __restrict__ eidx,
    const float* __restrict__ W1ss, const float* __restrict__ W1sv,
    const float* __restrict__ W1vs, const float* __restrict__ W1vvs,
    const float* __restrict__ W1vvv,
    const float* __restrict__ W2ss, const float* __restrict__ W2sv,
    const float* __restrict__ W2vs, const float* __restrict__ W2vvs,
    const float* __restrict__ W2vvv,
    const float* __restrict__ Lms, const float* __restrict__ Lmv,
    int E)
{
    extern __shared__ float sw[];
    float* w1ss  = sw;            // 4096
    float* w1sv  = w1ss  + 4096;  // 1024
    float* w1vs  = w1sv  + 1024;  // 1024
    float* w1vvs = w1vs  + 1024;  // 1024
    float* w1vvv = w1vvs + 1024;  // 512
    float* w2ss  = w1vvv + 512;   // 6144
    float* w2sv  = w2ss  + 6144;  // 2048
    float* w2vs  = w2sv  + 2048;  // 1024
    float* w2vvs = w2vs  + 1024;  // 3072
    float* w2vvv = w2vvs + 3072;  // 1024
    float* lms   = w2vvv + 1024;  // 512
    float* lmv   = lms   + 512;   // 128  -> total 21632 floats

    const float I2   = 0.70710678118654752f;   // 1/sqrt(2)
    const float I3   = 0.57735026918962576f;   // 1/sqrt(3)
    const float R128 = 0.08838834764831845f;   // 1/sqrt(128)
    int tid = threadIdx.x, nt = blockDim.x;
    // stage 1 norms: m1s=m2s=16, m1v=m2v=8
    load_scaled(w1ss,  W1ss,  4096 / 4, I2 / 16.f,      tid, nt);
    load_scaled(w1sv,  W1sv,  1024 / 4, I3 * R128,      tid, nt);
    load_scaled(w1vs,  W1vs,  1024 / 4, I3 * R128,      tid, nt);
    load_scaled(w1vvs, W1vvs, 1024 / 4, I2 * I3 / 8.f,  tid, nt);
    load_scaled(w1vvv, W1vvv,  512 / 4, I2 * I3 / 8.f,  tid, nt);
    // stage 2 norms: m1s=16, m2s=8, m1v=8, m2v=8
    load_scaled(w2ss,  W2ss,  6144 / 4, I2 * R128,      tid, nt);
    load_scaled(w2sv,  W2sv,  2048 / 4, I3 * R128,      tid, nt);
    load_scaled(w2vs,  W2vs,  1024 / 4, I3 / 8.f,       tid, nt);
    load_scaled(w2vvs, W2vvs, 3072 / 4, I2 * I3 / 8.f,  tid, nt);
    load_scaled(w2vvv, W2vvv, 1024 / 4, I2 * I3 / 8.f,  tid, nt);
    load_scaled(lms,   Lms,    512 / 4, 0.17677669529663687f, tid, nt); // 1/sqrt(32)
    load_scaled(lmv,   Lmv,    128 / 4, 0.25f,           tid, nt);      // 1/sqrt(16)
    __syncthreads();

    int e = blockIdx.x * blockDim.x + threadIdx.x;
    if (e >= E) return;
    int r = eidx[e];
    int c = eidx[E + e];

    float s1[16], v1[24], s2[16], v2[24], es[8], ev[24];
    {
        const float4* p;
        p = reinterpret_cast<const float4*>(node_s + (size_t)r * 16);
#pragma unroll
        for (int q = 0; q < 4; q++) reinterpret_cast<float4*>(s1)[q] = __ldg(p + q);
        p = reinterpret_cast<const float4*>(node_v + (size_t)r * 24);
#pragma unroll
        for (int q = 0; q < 6; q++) reinterpret_cast<float4*>(v1)[q] = __ldg(p + q);
        p = reinterpret_cast<const float4*>(node_s + (size_t)c * 16);
#pragma unroll
        for (int q = 0; q < 4; q++) reinterpret_cast<float4*>(s2)[q] = __ldg(p + q);
        p = reinterpret_cast<const float4*>(node_v + (size_t)c * 24);
#pragma unroll
        for (int q = 0; q < 6; q++) reinterpret_cast<float4*>(v2)[q] = __ldg(p + q);
        p = reinterpret_cast<const float4*>(edge_s + (size_t)e * 8);
#pragma unroll
        for (int q = 0; q < 2; q++) reinterpret_cast<float4*>(es)[q] = __ldg(p + q);
        p = reinterpret_cast<const float4*>(edge_v + (size_t)e * 24);
#pragma unroll
        for (int q = 0; q < 6; q++) reinterpret_cast<float4*>(ev)[q] = __ldg(p + q);
    }

    // stage 1: node(row) x node(col) -> 16s + 8v
    float ms[16], mv[24];
    fctp<16, 16, 8, 8, 16, 8>(s1, v1, s2, v2, w1ss, w1sv, w1vs, w1vvs, w1vvv, ms, mv);

    float msl[16], mvl[24];
#pragma unroll
    for (int t = 0; t < 16; t++) msl[t] = ms[t];
#pragma unroll
    for (int t = 0; t < 24; t++) mvl[t] = mv[t];

    // stage 2: intermediate x edge_attr -> 48s + 16v
    float hs[48], hv[48];
    fctp<16, 8, 8, 8, 48, 16>(msl, mvl, es, ev, w2ss, w2sv, w2vs, w2vvs, w2vvv, hs, hv);

    // gate + lin_messages_out
    float os[16], ov[24];
    gate_lin<48, 16, 16, 8>(hs, hv, lms, lmv, os, ov);

    // scatter-sum into destination node (col)
    float* dst = g_agg + (size_t)c * 40;
#pragma unroll
    for (int k = 0; k < 16; k++) atomicAdd(dst + k, os[k]);
#pragma unroll
    for (int t = 0; t < 24; t++) atomicAdd(dst + 16 + t, ov[t]);
}

__global__ __launch_bounds__(UPD_TPB) void update_kernel(
    const float* __restrict__ node_s, const float* __restrict__ node_v,
    const float* __restrict__ W3ss, const float* __restrict__ W3sv,
    const float* __restrict__ W3vs, const float* __restrict__ W3vvs,
    const float* __restrict__ W3vvv,
    const float* __restrict__ Lus, const float* __restrict__ Luv,
    float* __restrict__ out, int N)
{
    extern __shared__ float sw[];
    float* w3ss  = sw;             // 12288
    float* w3sv  = w3ss  + 12288;  // 2048
    float* w3vs  = w3sv  + 2048;   // 2048
    float* w3vvs = w3vs  + 2048;   // 3072
    float* w3vvv = w3vvs + 3072;   // 1024
    float* lus   = w3vvv + 1024;   // 512
    float* luv   = lus   + 512;    // 128  -> total 21120 floats

    const float I2   = 0.70710678118654752f;
    const float I3   = 0.57735026918962576f;
    const float R128 = 0.08838834764831845f;
    int tid = threadIdx.x, nt = blockDim.x;
    // stage 3 norms: m1s=16, m2s=16, m1v=8, m2v=8
    load_scaled(w3ss,  W3ss,  12288 / 4, I2 / 16.f,     tid, nt);
    load_scaled(w3sv,  W3sv,   2048 / 4, I3 * R128,     tid, nt);
    load_scaled(w3vs,  W3vs,   2048 / 4, I3 * R128,     tid, nt);
    load_scaled(w3vvs, W3vvs,  3072 / 4, I2 * I3 / 8.f, tid, nt);
    load_scaled(w3vvv, W3vvv,  1024 / 4, I2 * I3 / 8.f, tid, nt);
    load_scaled(lus,   Lus,     512 / 4, 0.17677669529663687f, tid, nt);
    load_scaled(luv,   Luv,     128 / 4, 0.25f,          tid, nt);
    __syncthreads();

    int n = blockIdx.x * blockDim.x + threadIdx.x;
    if (n >= N) return;

    float s1[16], v1[24], s2[16], v2[24];
    {
        const float4* p;
        p = reinterpret_cast<const float4*>(node_s + (size_t)n * 16);
#pragma unroll
        for (int q = 0; q < 4; q++) reinterpret_cast<float4*>(s1)[q] = __ldg(p + q);
        p = reinterpret_cast<const float4*>(node_v + (size_t)n * 24);
#pragma unroll
        for (int q = 0; q < 6; q++) reinterpret_cast<float4*>(v1)[q] = __ldg(p + q);
        const float4* pa = reinterpret_cast<const float4*>(g_agg + (size_t)n * 40);
#pragma unroll
        for (int q = 0; q < 4; q++) reinterpret_cast<float4*>(s2)[q] = pa[q];
#pragma unroll
        for (int q = 0; q < 6; q++) reinterpret_cast<float4*>(v2)[q] = pa[4 + q];
    }

    float hs[48], hv[48];
    fctp<16, 16, 8, 8, 48, 16>(s1, v1, s2, v2, w3ss, w3sv, w3vs, w3vvs, w3vvv, hs, hv);

    float os[16], ov[24];
    gate_lin<48, 16, 16, 8>(hs, hv, lus, luv, os, ov);

    float* o = out + (size_t)n * 40;
#pragma unroll
    for (int k = 0; k < 16; k++) o[k] = os[k];
#pragma unroll
    for (int t = 0; t < 24; t++) o[16 + t] = ov[t];
}

// ---------------- launch ----------------
extern "C" void kernel_launch(void* const* d_in, const int* in_sizes, int n_in,
                              void* d_out, int out_size) {
    const float* node_s = (const float*)d_in[0];
    const float* node_v = (const float*)d_in[1];
    // d_in[2] = pos (unused by the reference)
    const float* edge_s = (const float*)d_in[3];
    const float* edge_v = (const float*)d_in[4];
    const int*   eidx   = (const int*)d_in[5];
    const float* W1ss = (const float*)d_in[6];
    const float* W1sv = (const float*)d_in[7];
    const float* W1vs = (const float*)d_in[8];
    const float* W1vvs = (const float*)d_in[9];
    const float* W1vvv = (const float*)d_in[10];
    const float* W2ss = (const float*)d_in[11];
    const float* W2sv = (const float*)d_in[12];
    const float* W2vs = (const float*)d_in[13];
    const float* W2vvs = (const float*)d_in[14];
    const float* W2vvv = (const float*)d_in[15];
    const float* Lms = (const float*)d_in[16];
    const float* Lmv = (const float*)d_in[17];
    const float* W3ss = (const float*)d_in[18];
    const float* W3sv = (const float*)d_in[19];
    const float* W3vs = (const float*)d_in[20];
    const float* W3vvs = (const float*)d_in[21];
    const float* W3vvv = (const float*)d_in[22];
    const float* Lus = (const float*)d_in[23];
    const float* Luv = (const float*)d_in[24];
    float* out = (float*)d_out;

    int N = in_sizes[0] / 16;
    int E = in_sizes[3] / 8;

    size_t smem_e = 21632 * sizeof(float); // 86528 B
    size_t smem_u = 21120 * sizeof(float); // 84480 B
    cudaFuncSetAttribute(edge_kernel, cudaFuncAttributeMaxDynamicSharedMemorySize, (int)smem_e);
    cudaFuncSetAttribute(update_kernel, cudaFuncAttributeMaxDynamicSharedMemorySize, (int)smem_u);

    zero_agg_kernel<<<(N * 40 + 255) / 256, 256>>>(N * 40);
    edge_kernel<<<(E + EDGE_TPB - 1) / EDGE_TPB, EDGE_TPB, smem_e>>>(
        node_s, node_v, edge_s, edge_v, eidx,
        W1ss, W1sv, W1vs, W1vvs, W1vvv,
        W2ss, W2sv, W2vs, W2vvs, W2vvv,
        Lms, Lmv, E);
    update_kernel<<<(N + UPD_TPB - 1) / UPD_TPB, UPD_TPB, smem_u>>>(
        node_s, node_v, W3ss, W3sv, W3vs, W3vvs, W3vvv, Lus, Luv, out, N);
}

// round 2
// speedup vs baseline: 1.5090x; 1.5090x over previous
#include <cuda_runtime.h>
#include <math.h>

#define TPB 128

// Static scratch (problem sizes fixed: N=50000, E=400000)
__device__ float g_agg[50048 * 40];     // per-node aggregation [N,40]
__device__ float g_mid[400000 * 40];    // per-edge stage-1 intermediate [E,40]

// ---------------- cooperative scaled weight load ----------------
__device__ __forceinline__ void load_scaled(float* __restrict__ dst,
                                            const float* __restrict__ src,
                                            int n4, float sc, int tid, int nt) {
    for (int t = tid; t < n4; t += nt) {
        float4 v = reinterpret_cast<const float4*>(src)[t];
        v.x *= sc; v.y *= sc; v.z *= sc; v.w *= sc;
        reinterpret_cast<float4*>(dst)[t] = v;
    }
}

__device__ __forceinline__ void load_vec(float* dst, const float* __restrict__ src, int n4) {
#pragma unroll
    for (int q = 0; q < 8; q++)
        if (q < n4) reinterpret_cast<float4*>(dst)[q] =
            __ldg(reinterpret_cast<const float4*>(src) + q);
}

// ---------------- scalar-output paths (0x0->0, 1x1->0), k-chunked ----------------
template<int M1S, int M2S, int M1V, int M2V, int KS, int KO, int KC>
__device__ __forceinline__ void fctp_scalar(
    const float* s1, const float* v1, const float* s2, const float* v2,
    const float* __restrict__ wss, const float* __restrict__ wvvs,
    float (&so)[KC])
{
#pragma unroll
    for (int k = 0; k < KC; k++) so[k] = 0.f;
#pragma unroll 1
    for (int i = 0; i < M1S; i++) {
        float a = s1[i];
#pragma unroll 1
        for (int j = 0; j < M2S; j++) {
            float p = a * s2[j];
            const float4* w = reinterpret_cast<const float4*>(wss + (i * M2S + j) * KS + KO);
#pragma unroll
            for (int k = 0; k < KC / 4; k++) {
                float4 ww = w[k];
                so[4 * k + 0] += p * ww.x; so[4 * k + 1] += p * ww.y;
                so[4 * k + 2] += p * ww.z; so[4 * k + 3] += p * ww.w;
            }
        }
    }
#pragma unroll 1
    for (int i = 0; i < M1V; i++) {
        float ax = v1[3 * i + 0], ay = v1[3 * i + 1], az = v1[3 * i + 2];
#pragma unroll 1
        for (int j = 0; j < M2V; j++) {
            float d = ax * v2[3 * j + 0] + ay * v2[3 * j + 1] + az * v2[3 * j + 2];
            const float4* w = reinterpret_cast<const float4*>(wvvs + (i * M2V + j) * KS + KO);
#pragma unroll
            for (int k = 0; k < KC / 4; k++) {
                float4 ww = w[k];
                so[4 * k + 0] += d * ww.x; so[4 * k + 1] += d * ww.y;
                so[4 * k + 2] += d * ww.z; so[4 * k + 3] += d * ww.w;
            }
        }
    }
}

// ---------------- vector-output paths (0x1->1, 1x0->1, 1x1->1) ----------------
template<int M1S, int M2S, int M1V, int M2V, int KV>
__device__ __forceinline__ void fctp_vector(
    const float* s1, const float* v1, const float* s2, const float* v2,
    const float* __restrict__ wsv, const float* __restrict__ wvs,
    const float* __restrict__ wvvv,
    float (&vo)[KV * 3])
{
#pragma unroll
    for (int k = 0; k < KV * 3; k++) vo[k] = 0.f;
    // 0 x 1 -> 1 : contract s1 with W over i first (per j)
#pragma unroll 1
    for (int j = 0; j < M2V; j++) {
        float A[KV];
#pragma unroll
        for (int k = 0; k < KV; k++) A[k] = 0.f;
#pragma unroll 1
        for (int i = 0; i < M1S; i++) {
            float a = s1[i];
            const float4* w = reinterpret_cast<const float4*>(wsv + (i * M2V + j) * KV);
#pragma unroll
            for (int k = 0; k < KV / 4; k++) {
                float4 ww = w[k];
                A[4 * k + 0] += a * ww.x; A[4 * k + 1] += a * ww.y;
                A[4 * k + 2] += a * ww.z; A[4 * k + 3] += a * ww.w;
            }
        }
        float bx = v2[3 * j + 0], by = v2[3 * j + 1], bz = v2[3 * j + 2];
#pragma unroll
        for (int k = 0; k < KV; k++) {
            vo[3 * k + 0] += A[k] * bx; vo[3 * k + 1] += A[k] * by; vo[3 * k + 2] += A[k] * bz;
        }
    }
    // 1 x 0 -> 1 : contract s2 with W over j first (per i)
#pragma unroll 1
    for (int i = 0; i < M1V; i++) {
        float A[KV];
#pragma unroll
        for (int k = 0; k < KV; k++) A[k] = 0.f;
#pragma unroll 1
        for (int j = 0; j < M2S; j++) {
            float b = s2[j];
            const float4* w = reinterpret_cast<const float4*>(wvs + (i * M2S + j) * KV);
#pragma unroll
            for (int k = 0; k < KV / 4; k++) {
                float4 ww = w[k];
                A[4 * k + 0] += b * ww.x; A[4 * k + 1] += b * ww.y;
                A[4 * k + 2] += b * ww.z; A[4 * k + 3] += b * ww.w;
            }
        }
        float ax = v1[3 * i + 0], ay = v1[3 * i + 1], az = v1[3 * i + 2];
#pragma unroll
        for (int k = 0; k < KV; k++) {
            vo[3 * k + 0] += A[k] * ax; vo[3 * k + 1] += A[k] * ay; vo[3 * k + 2] += A[k] * az;
        }
    }
    // 1 x 1 -> 1 (cross)
#pragma unroll 1
    for (int i = 0; i < M1V; i++) {
        float ax = v1[3 * i + 0], ay = v1[3 * i + 1], az = v1[3 * i + 2];
#pragma unroll 1
        for (int j = 0; j < M2V; j++) {
            float bx = v2[3 * j + 0], by = v2[3 * j + 1], bz = v2[3 * j + 2];
            float cx = ay * bz - az * by;
            float cy = az * bx - ax * bz;
            float cz = ax * by - ay * bx;
            const float4* w = reinterpret_cast<const float4*>(wvvv + (i * M2V + j) * KV);
#pragma unroll
            for (int k = 0; k < KV / 4; k++) {
                float4 ww = w[k];
                vo[12 * k + 0] += cx * ww.x; vo[12 * k + 1]  += cy * ww.x; vo[12 * k + 2]  += cz * ww.x;
                vo[12 * k + 3] += cx * ww.y; vo[12 * k + 4]  += cy * ww.y; vo[12 * k + 5]  += cz * ww.y;
                vo[12 * k + 6] += cx * ww.z; vo[12 * k + 7]  += cy * ww.z; vo[12 * k + 8]  += cz * ww.z;
                vo[12 * k + 9] += cx * ww.w; vo[12 * k + 10] += cy * ww.w; vo[12 * k + 11] += cz * ww.w;
            }
        }
    }
}

__device__ __forceinline__ float silu_f(float x) {
    return x * __fdividef(1.f, 1.f + __expf(-x));
}
__device__ __forceinline__ float sigm_f(float x) {
    return __fdividef(1.f, 1.f + __expf(-x));
}

// ---------------- kernels ----------------
__global__ void zero_agg_kernel(int n) {
    int i = blockIdx.x * blockDim.x + threadIdx.x;
    if (i < n) g_agg[i] = 0.f;
}

// Stage 1: per-edge FCTP(node[row], node[col]) -> g_mid[e, 40]
__global__ __launch_bounds__(TPB) void stage1_kernel(
    const float* __restrict__ node_s, const float* __restrict__ node_v,
    const int* __restrict__ eidx,
    const float* __restrict__ W1ss, const float* __restrict__ W1sv,
    const float* __restrict__ W1vs, const float* __restrict__ W1vvs,
    const float* __restrict__ W1vvv, int E)
{
    extern __shared__ float sw[];
    float* w1ss  = sw;            // 4096
    float* w1sv  = w1ss  + 4096;  // 1024
    float* w1vs  = w1sv  + 1024;  // 1024
    float* w1vvs = w1vs  + 1024;  // 1024
    float* w1vvv = w1vvs + 1024;  // 512  -> 7680 floats

    const float I2 = 0.70710678118654752f, I3 = 0.57735026918962576f;
    const float R128 = 0.08838834764831845f;
    int tid = threadIdx.x, nt = blockDim.x;
    load_scaled(w1ss,  W1ss,  1024, I2 / 16.f,     tid, nt);
    load_scaled(w1sv,  W1sv,   256, I3 * R128,     tid, nt);
    load_scaled(w1vs,  W1vs,   256, I3 * R128,     tid, nt);
    load_scaled(w1vvs, W1vvs,  256, I2 * I3 / 8.f, tid, nt);
    load_scaled(w1vvv, W1vvv,  128, I2 * I3 / 8.f, tid, nt);
    __syncthreads();

    int e = blockIdx.x * blockDim.x + threadIdx.x;
    if (e >= E) return;
    int r = eidx[e];
    int c = eidx[E + e];

    float s1[16], v1[24], s2[16], v2[24];
    load_vec(s1, node_s + (size_t)r * 16, 4);
    load_vec(v1, node_v + (size_t)r * 24, 6);
    load_vec(s2, node_s + (size_t)c * 16, 4);
    load_vec(v2, node_v + (size_t)c * 24, 6);

    float ms[16], mv[24];
    fctp_scalar<16, 16, 8, 8, 16, 0, 16>(s1, v1, s2, v2, w1ss, w1vvs, ms);
    fctp_vector<16, 16, 8, 8, 8>(s1, v1, s2, v2, w1sv, w1vs, w1vvv, mv);

    float* o = g_mid + (size_t)e * 40;
#pragma unroll
    for (int q = 0; q < 4; q++) reinterpret_cast<float4*>(o)[q] = reinterpret_cast<float4*>(ms)[q];
#pragma unroll
    for (int q = 0; q < 6; q++) reinterpret_cast<float4*>(o)[4 + q] = reinterpret_cast<float4*>(mv)[q];
}

// Stage 2: per-edge FCTP(mid, edge_attr) -> gate -> linear -> atomic scatter to g_agg
__global__ __launch_bounds__(TPB) void stage2_kernel(
    const float* __restrict__ edge_s, const float* __restrict__ edge_v,
    const int* __restrict__ eidx,
    const float* __restrict__ W2ss, const float* __restrict__ W2sv,
    const float* __restrict__ W2vs, const float* __restrict__ W2vvs,
    const float* __restrict__ W2vvv,
    const float* __restrict__ Lms, const float* __restrict__ Lmv, int E)
{
    extern __shared__ float sw[];
    float* w2ss  = sw;            // 6144
    float* w2sv  = w2ss  + 6144;  // 2048
    float* w2vs  = w2sv  + 2048;  // 1024
    float* w2vvs = w2vs  + 1024;  // 3072
    float* w2vvv = w2vvs + 3072;  // 1024
    float* lms   = w2vvv + 1024;  // 512
    float* lmv   = lms   + 512;   // 128  -> 13952 floats (55.8KB)

    const float I2 = 0.70710678118654752f, I3 = 0.57735026918962576f;
    const float R128 = 0.08838834764831845f;
    int tid = threadIdx.x, nt = blockDim.x;
    load_scaled(w2ss,  W2ss,  1536, I2 * R128,     tid, nt);
    load_scaled(w2sv,  W2sv,   512, I3 * R128,     tid, nt);
    load_scaled(w2vs,  W2vs,   256, I3 / 8.f,      tid, nt);
    load_scaled(w2vvs, W2vvs,  768, I2 * I3 / 8.f, tid, nt);
    load_scaled(w2vvv, W2vvv,  256, I2 * I3 / 8.f, tid, nt);
    load_scaled(lms,   Lms,    128, 0.17677669529663687f, tid, nt);
    load_scaled(lmv,   Lmv,     32, 0.25f,          tid, nt);
    __syncthreads();

    int e = blockIdx.x * blockDim.x + threadIdx.x;
    if (e >= E) return;
    int c = eidx[E + e];

    float ms[16], mv[24], es[8], ev[24];
    {
        const float* m = g_mid + (size_t)e * 40;
#pragma unroll
        for (int q = 0; q < 4; q++) reinterpret_cast<float4*>(ms)[q] = reinterpret_cast<const float4*>(m)[q];
#pragma unroll
        for (int q = 0; q < 6; q++) reinterpret_cast<float4*>(mv)[q] = reinterpret_cast<const float4*>(m)[4 + q];
    }
    load_vec(es, edge_s + (size_t)e * 8, 2);
    load_vec(ev, edge_v + (size_t)e * 24, 6);

    // ---- pass A: scalar outputs k in [0,32): silu + Lms immediately ----
    float os[16];
#pragma unroll
    for (int k = 0; k < 16; k++) os[k] = 0.f;
    {
        float soA[32];
        fctp_scalar<16, 8, 8, 8, 48, 0, 32>(ms, mv, es, ev, w2ss, w2vvs, soA);
#pragma unroll 1
        for (int t = 0; t < 32; t++) {
            float a = silu_f(soA[t]);
            const float4* w = reinterpret_cast<const float4*>(lms + t * 16);
#pragma unroll
            for (int k = 0; k < 4; k++) {
                float4 ww = w[k];
                os[4 * k + 0] += a * ww.x; os[4 * k + 1] += a * ww.y;
                os[4 * k + 2] += a * ww.z; os[4 * k + 3] += a * ww.w;
            }
        }
    }

    // ---- pass B: gate scalars k in [32,48) + vector outputs, gate, Lmv ----
    float ov[24];
#pragma unroll
    for (int k = 0; k < 24; k++) ov[k] = 0.f;
    {
        float soB[16];
        fctp_scalar<16, 8, 8, 8, 48, 32, 16>(ms, mv, es, ev, w2ss, w2vvs, soB);
        float vo[48];
        fctp_vector<16, 8, 8, 8, 16>(ms, mv, es, ev, w2sv, w2vs, w2vvv, vo);
#pragma unroll 1
        for (int t = 0; t < 16; t++) {
            float g = sigm_f(soB[t]);
            float ax = vo[3 * t + 0] * g, ay = vo[3 * t + 1] * g, az = vo[3 * t + 2] * g;
            const float4* w = reinterpret_cast<const float4*>(lmv + t * 8);
#pragma unroll
            for (int k = 0; k < 2; k++) {
                float4 ww = w[k];
                ov[12 * k + 0] += ax * ww.x; ov[12 * k + 1]  += ay * ww.x; ov[12 * k + 2]  += az * ww.x;
                ov[12 * k + 3] += ax * ww.y; ov[12 * k + 4]  += ay * ww.y; ov[12 * k + 5]  += az * ww.y;
                ov[12 * k + 6] += ax * ww.z; ov[12 * k + 7]  += ay * ww.z; ov[12 * k + 8]  += az * ww.z;
                ov[12 * k + 9] += ax * ww.w; ov[12 * k + 10] += ay * ww.w; ov[12 * k + 11] += az * ww.w;
            }
        }
    }

    float* dst = g_agg + (size_t)c * 40;
#pragma unroll
    for (int k = 0; k < 16; k++) atomicAdd(dst + k, os[k]);
#pragma unroll
    for (int t = 0; t < 24; t++) atomicAdd(dst + 16 + t, ov[t]);
}

// Update: per-node FCTP(node, agg) -> gate -> linear -> out
__global__ __launch_bounds__(TPB) void update_kernel(
    const float* __restrict__ node_s, const float* __restrict__ node_v,
    const float* __restrict__ W3ss, const float* __restrict__ W3sv,
    const float* __restrict__ W3vs, const float* __restrict__ W3vvs,
    const float* __restrict__ W3vvv,
    const float* __restrict__ Lus, const float* __restrict__ Luv,
    float* __restrict__ out, int N)
{
    extern __shared__ float sw[];
    float* w3ss  = sw;             // 12288
    float* w3sv  = w3ss  + 12288;  // 2048
    float* w3vs  = w3sv  + 2048;   // 2048
    float* w3vvs = w3vs  + 2048;   // 3072
    float* w3vvv = w3vvs + 3072;   // 1024
    float* lus   = w3vvv + 1024;   // 512
    float* luv   = lus   + 512;    // 128  -> 21120 floats (84.5KB)

    const float I2 = 0.70710678118654752f, I3 = 0.57735026918962576f;
    const float R128 = 0.08838834764831845f;
    int tid = threadIdx.x, nt = blockDim.x;
    load_scaled(w3ss,  W3ss,  3072, I2 / 16.f,     tid, nt);
    load_scaled(w3sv,  W3sv,   512, I3 * R128,     tid, nt);
    load_scaled(w3vs,  W3vs,   512, I3 * R128,     tid, nt);
    load_scaled(w3vvs, W3vvs,  768, I2 * I3 / 8.f, tid, nt);
    load_scaled(w3vvv, W3vvv,  256, I2 * I3 / 8.f, tid, nt);
    load_scaled(lus,   Lus,    128, 0.17677669529663687f, tid, nt);
    load_scaled(luv,   Luv,     32, 0.25f,          tid, nt);
    __syncthreads();

    int n = blockIdx.x * blockDim.x + threadIdx.x;
    if (n >= N) return;

    float s1[16], v1[24], s2[16], v2[24];
    load_vec(s1, node_s + (size_t)n * 16, 4);
    load_vec(v1, node_v + (size_t)n * 24, 6);
    {
        const float* a = g_agg + (size_t)n * 40;
#pragma unroll
        for (int q = 0; q < 4; q++) reinterpret_cast<float4*>(s2)[q] = reinterpret_cast<const float4*>(a)[q];
#pragma unroll
        for (int q = 0; q < 6; q++) reinterpret_cast<float4*>(v2)[q] = reinterpret_cast<const float4*>(a)[4 + q];
    }

    float os[16];
#pragma unroll
    for (int k = 0; k < 16; k++) os[k] = 0.f;
    {
        float soA[32];
        fctp_scalar<16, 16, 8, 8, 48, 0, 32>(s1, v1, s2, v2, w3ss, w3vvs, soA);
#pragma unroll 1
        for (int t = 0; t < 32; t++) {
            float a = silu_f(soA[t]);
            const float4* w = reinterpret_cast<const float4*>(lus + t * 16);
#pragma unroll
            for (int k = 0; k < 4; k++) {
                float4 ww = w[k];
                os[4 * k + 0] += a * ww.x; os[4 * k + 1] += a * ww.y;
                os[4 * k + 2] += a * ww.z; os[4 * k + 3] += a * ww.w;
            }
        }
    }

    float ov[24];
#pragma unroll
    for (int k = 0; k < 24; k++) ov[k] = 0.f;
    {
        float soB[16];
        fctp_scalar<16, 16, 8, 8, 48, 32, 16>(s1, v1, s2, v2, w3ss, w3vvs, soB);
        float vo[48];
        fctp_vector<16, 16, 8, 8, 16>(s1, v1, s2, v2, w3sv, w3vs, w3vvv, vo);
#pragma unroll 1
        for (int t = 0; t < 16; t++) {
            float g = sigm_f(soB[t]);
            float ax = vo[3 * t + 0] * g, ay = vo[3 * t + 1] * g, az = vo[3 * t + 2] * g;
            const float4* w = reinterpret_cast<const float4*>(luv + t * 8);
#pragma unroll
            for (int k = 0; k < 2; k++) {
                float4 ww = w[k];
                ov[12 * k + 0] += ax * ww.x; ov[12 * k + 1]  += ay * ww.x; ov[12 * k + 2]  += az * ww.x;
                ov[12 * k + 3] += ax * ww.y; ov[12 * k + 4]  += ay * ww.y; ov[12 * k + 5]  += az * ww.y;
                ov[12 * k + 6] += ax * ww.z; ov[12 * k + 7]  += ay * ww.z; ov[12 * k + 8]  += az * ww.z;
                ov[12 * k + 9] += ax * ww.w; ov[12 * k + 10] += ay * ww.w; ov[12 * k + 11] += az * ww.w;
            }
        }
    }

    float* o = out + (size_t)n * 40;
#pragma unroll
    for (int q = 0; q < 4; q++) reinterpret_cast<float4*>(o)[q] = reinterpret_cast<float4*>(os)[q];
#pragma unroll
    for (int q = 0; q < 6; q++) reinterpret_cast<float4*>(o)[4 + q] = reinterpret_cast<float4*>(ov)[q];
}

// ---------------- launch ----------------
extern "C" void kernel_launch(void* const* d_in, const int* in_sizes, int n_in,
                              void* d_out, int out_size) {
    const float* node_s = (const float*)d_in[0];
    const float* node_v = (const float*)d_in[1];
    const float* edge_s = (const float*)d_in[3];
    const float* edge_v = (const float*)d_in[4];
    const int*   eidx   = (const int*)d_in[5];
    const float* W1ss = (const float*)d_in[6];
    const float* W1sv = (const float*)d_in[7];
    const float* W1vs = (const float*)d_in[8];
    const float* W1vvs = (const float*)d_in[9];
    const float* W1vvv = (const float*)d_in[10];
    const float* W2ss = (const float*)d_in[11];
    const float* W2sv = (const float*)d_in[12];
    const float* W2vs = (const float*)d_in[13];
    const float* W2vvs = (const float*)d_in[14];
    const float* W2vvv = (const float*)d_in[15];
    const float* Lms = (const float*)d_in[16];
    const float* Lmv = (const float*)d_in[17];
    const float* W3ss = (const float*)d_in[18];
    const float* W3sv = (const float*)d_in[19];
    const float* W3vs = (const float*)d_in[20];
    const float* W3vvs = (const float*)d_in[21];
    const float* W3vvv = (const float*)d_in[22];
    const float* Lus = (const float*)d_in[23];
    const float* Luv = (const float*)d_in[24];
    float* out = (float*)d_out;

    int N = in_sizes[0] / 16;
    int E = in_sizes[3] / 8;

    size_t smem1 = 7680 * sizeof(float);   // 30.7KB
    size_t smem2 = 13952 * sizeof(float);  // 55.8KB
    size_t smem3 = 21120 * sizeof(float);  // 84.5KB
    cudaFuncSetAttribute(stage1_kernel, cudaFuncAttributeMaxDynamicSharedMemorySize, (int)smem1);
    cudaFuncSetAttribute(stage2_kernel, cudaFuncAttributeMaxDynamicSharedMemorySize, (int)smem2);
    cudaFuncSetAttribute(update_kernel, cudaFuncAttributeMaxDynamicSharedMemorySize, (int)smem3);

    zero_agg_kernel<<<(N * 40 + 255) / 256, 256>>>(N * 40);
    stage1_kernel<<<(E + TPB - 1) / TPB, TPB, smem1>>>(
        node_s, node_v, eidx, W1ss, W1sv, W1vs, W1vvs, W1vvv, E);
    stage2_kernel<<<(E + TPB - 1) / TPB, TPB, smem2>>>(
        edge_s, edge_v, eidx, W2ss, W2sv, W2vs, W2vvs, W2vvv, Lms, Lmv, E);
    update_kernel<<<(N + TPB - 1) / TPB, TPB, smem3>>>(
        node_s, node_v, W3ss, W3sv, W3vs, W3vvs, W3vvv, Lus, Luv, out, N);
}

// round 4
// speedup vs baseline: 1.8517x; 1.2271x over previous
#include <cuda_runtime.h>

// ---------------- scratch (sizes fixed for this problem) ----------------
__device__ float g_agg [50048  * 80];   // per-node gated sums: 32 silu'd scalars + 48 vec comps
__device__ float g_agg2[50048  * 40];   // after Lms/Lmv fold: 16 s + 24 v
__device__ float g_mid [400000 * 40];   // stage-1 per-edge intermediate
__device__ float g_gate[16 * 400000];   // sigmoid gates, t-major [16][E]
__device__ float g_hid [48 * 50048];    // update hidden scalars (silu'd / sigm'd), t-major
__device__ float g_hidv[48 * 50048];    // update gated vector comps, (k*3+c)-major

#define I2f   0.70710678118654752f
#define I3f   0.57735026918962576f
#define R128f 0.08838834764831845f
#define R32f  0.17677669529663687f

__device__ __forceinline__ float sigm_f(float x) {
    return __fdividef(1.f, 1.f + __expf(-x));
}

// cooperative scaled weight load (full tensor)
__device__ __forceinline__ void wload(float* __restrict__ dst, const float* __restrict__ src,
                                      int nf4, float sc, int tid, int nt) {
    for (int t = tid; t < nf4; t += nt) {
        float4 v = reinterpret_cast<const float4*>(src)[t];
        v.x *= sc; v.y *= sc; v.z *= sc; v.w *= sc;
        reinterpret_cast<float4*>(dst)[t] = v;
    }
}
// cooperative scaled k-slice load: src rows of srcF4 float4s, take dstF4 at off4
__device__ __forceinline__ void wslice(float* __restrict__ dst, const float* __restrict__ src,
                                       int rows, int srcF4, int dstF4, int off4,
                                       float sc, int tid) {
    int n = rows * dstF4;
    for (int t = tid; t < n; t += 128) {
        int r = t / dstF4, o = t - r * dstF4;
        float4 v = reinterpret_cast<const float4*>(src)[r * srcF4 + off4 + o];
        v.x *= sc; v.y *= sc; v.z *= sc; v.w *= sc;
        reinterpret_cast<float4*>(dst)[t] = v;
    }
}

template<int K4>
__device__ __forceinline__ void fma_k(float* acc, const float* __restrict__ w, float p) {
#pragma unroll
    for (int k = 0; k < K4; k++) {
        float4 ww = reinterpret_cast<const float4*>(w)[k];
        acc[4 * k + 0] += p * ww.x; acc[4 * k + 1] += p * ww.y;
        acc[4 * k + 2] += p * ww.z; acc[4 * k + 3] += p * ww.w;
    }
}
__device__ __forceinline__ void fma_vo8(float* vo, const float* A, float bx, float by, float bz) {
#pragma unroll
    for (int k = 0; k < 8; k++) {
        vo[3 * k + 0] += A[k] * bx; vo[3 * k + 1] += A[k] * by; vo[3 * k + 2] += A[k] * bz;
    }
}
__device__ __forceinline__ void fma_cross8(float* vo, const float* __restrict__ w,
                                           float cx, float cy, float cz) {
#pragma unroll
    for (int q = 0; q < 2; q++) {
        float4 ww = reinterpret_cast<const float4*>(w)[q];
        vo[12 * q + 0]  += cx * ww.x; vo[12 * q + 1]  += cy * ww.x; vo[12 * q + 2]  += cz * ww.x;
        vo[12 * q + 3]  += cx * ww.y; vo[12 * q + 4]  += cy * ww.y; vo[12 * q + 5]  += cz * ww.y;
        vo[12 * q + 6]  += cx * ww.z; vo[12 * q + 7]  += cy * ww.z; vo[12 * q + 8]  += cz * ww.z;
        vo[12 * q + 9]  += cx * ww.w; vo[12 * q + 10] += cy * ww.w; vo[12 * q + 11] += cz * ww.w;
    }
}
__device__ __forceinline__ void ld_f(float* dst, const float* __restrict__ src, int nf4) {
#pragma unroll
    for (int q = 0; q < 6; q++)
        if (q < nf4) reinterpret_cast<float4*>(dst)[q] =
            __ldg(reinterpret_cast<const float4*>(src) + q);
}

// ---------------- kernels ----------------
__global__ void zero_kernel(int n) {
    int i = blockIdx.x * 256 + threadIdx.x;
    if (i < n) g_agg[i] = 0.f;
}

// stage1 scalar paths: ms[16] -> g_mid[e][0:16)
__global__ __launch_bounds__(128, 6) void stage1_s_kernel(
    const float* __restrict__ ns, const float* __restrict__ nv,
    const int* __restrict__ eidx,
    const float* __restrict__ W1ss, const float* __restrict__ W1vvs, int E)
{
    __shared__ float wss[4096], wd[1024];
    int tid = threadIdx.x;
    wload(wss, W1ss, 1024, I2f / 16.f, tid, 128);
    wload(wd, W1vvs, 256, I2f * I3f / 8.f, tid, 128);
    __syncthreads();
    int e = blockIdx.x * 128 + tid;
    if (e >= E) return;
    int r = eidx[e], c = eidx[E + e];

    float acc[16];
#pragma unroll
    for (int k = 0; k < 16; k++) acc[k] = 0.f;
    {
        float s1[16], s2[16];
        ld_f(s1, ns + (size_t)r * 16, 4);
        ld_f(s2, ns + (size_t)c * 16, 4);
#pragma unroll 1
        for (int i = 0; i < 16; i++) {
            float a = s1[i];
#pragma unroll 2
            for (int j = 0; j < 16; j++)
                fma_k<4>(acc, &wss[(i * 16 + j) * 16], a * s2[j]);
        }
    }
    {
        float v1[24], v2[24];
        ld_f(v1, nv + (size_t)r * 24, 6);
        ld_f(v2, nv + (size_t)c * 24, 6);
#pragma unroll 1
        for (int i = 0; i < 8; i++) {
            float ax = v1[3 * i], ay = v1[3 * i + 1], az = v1[3 * i + 2];
#pragma unroll 2
            for (int j = 0; j < 8; j++) {
                float d = ax * v2[3 * j] + ay * v2[3 * j + 1] + az * v2[3 * j + 2];
                fma_k<4>(acc, &wd[(i * 8 + j) * 16], d);
            }
        }
    }
    float* o = &g_mid[(size_t)e * 40];
#pragma unroll
    for (int q = 0; q < 4; q++)
        reinterpret_cast<float4*>(o)[q] = reinterpret_cast<float4*>(acc)[q];
}

// stage1 vector paths: mv[8][3] -> g_mid[e][16:40)
__global__ __launch_bounds__(128, 6) void stage1_v_kernel(
    const float* __restrict__ ns, const float* __restrict__ nv,
    const int* __restrict__ eidx,
    const float* __restrict__ W1sv, const float* __restrict__ W1vs,
    const float* __restrict__ W1vvv, int E)
{
    __shared__ float wsv[1024], wvs[1024], wvvv[512];
    int tid = threadIdx.x;
    wload(wsv, W1sv, 256, I3f * R128f, tid, 128);
    wload(wvs, W1vs, 256, I3f * R128f, tid, 128);
    wload(wvvv, W1vvv, 128, I2f * I3f / 8.f, tid, 128);
    __syncthreads();
    int e = blockIdx.x * 128 + tid;
    if (e >= E) return;
    int r = eidx[e], c = eidx[E + e];

    float vo[24];
#pragma unroll
    for (int k = 0; k < 24; k++) vo[k] = 0.f;
    float v2[24];
    ld_f(v2, nv + (size_t)c * 24, 6);
    {   // 0x1 -> 1
        float s1[16];
        ld_f(s1, ns + (size_t)r * 16, 4);
#pragma unroll 1
        for (int j = 0; j < 8; j++) {
            float A[8];
#pragma unroll
            for (int k = 0; k < 8; k++) A[k] = 0.f;
#pragma unroll 2
            for (int i = 0; i < 16; i++)
                fma_k<2>(A, &wsv[(i * 8 + j) * 8], s1[i]);
            fma_vo8(vo, A, v2[3 * j], v2[3 * j + 1], v2[3 * j + 2]);
        }
    }
    float v1[24];
    ld_f(v1, nv + (size_t)r * 24, 6);
    {   // 1x0 -> 1
        float s2[16];
        ld_f(s2, ns + (size_t)c * 16, 4);
#pragma unroll 1
        for (int i = 0; i < 8; i++) {
            float A[8];
#pragma unroll
            for (int k = 0; k < 8; k++) A[k] = 0.f;
#pragma unroll 2
            for (int j = 0; j < 16; j++)
                fma_k<2>(A, &wvs[(i * 16 + j) * 8], s2[j]);
            fma_vo8(vo, A, v1[3 * i], v1[3 * i + 1], v1[3 * i + 2]);
        }
    }
    // 1x1 -> 1
#pragma unroll 1
    for (int i = 0; i < 8; i++) {
        float ax = v1[3 * i], ay = v1[3 * i + 1], az = v1[3 * i + 2];
#pragma unroll 1
        for (int j = 0; j < 8; j++) {
            float bx = v2[3 * j], by = v2[3 * j + 1], bz = v2[3 * j + 2];
            fma_cross8(vo, &wvvv[(i * 8 + j) * 8],
                       ay * bz - az * by, az * bx - ax * bz, ax * by - ay * bx);
        }
    }
    float* o = &g_mid[(size_t)e * 40 + 16];
#pragma unroll
    for (int q = 0; q < 6; q++)
        reinterpret_cast<float4*>(o)[q] = reinterpret_cast<float4*>(vo)[q];
}

// stage2 scalar paths, 3 k-chunks of 16. chunks 0,1: silu -> atomic agg. chunk 2: sigm -> g_gate.
__global__ __launch_bounds__(128, 5) void stage2_s_kernel(
    const float* __restrict__ edge_s, const float* __restrict__ edge_v,
    const int* __restrict__ eidx,
    const float* __restrict__ W2ss, const float* __restrict__ W2vvs, int E)
{
    __shared__ float ws[2048], wd[1024];
    int tid = threadIdx.x;
    int e = blockIdx.x * 128 + tid;
    bool act = e < E;
    int c = 0;
    float ms[16], mv[24], es[8], ev[24];
    if (act) {
        c = eidx[E + e];
        const float* m = &g_mid[(size_t)e * 40];
#pragma unroll
        for (int q = 0; q < 4; q++) reinterpret_cast<float4*>(ms)[q] = reinterpret_cast<const float4*>(m)[q];
#pragma unroll
        for (int q = 0; q < 6; q++) reinterpret_cast<float4*>(mv)[q] = reinterpret_cast<const float4*>(m)[4 + q];
        ld_f(es, edge_s + (size_t)e * 8, 2);
        ld_f(ev, edge_v + (size_t)e * 24, 6);
    }
#pragma unroll 1
    for (int ch = 0; ch < 3; ch++) {
        __syncthreads();
        wslice(ws, W2ss, 128, 12, 4, ch * 4, I2f * R128f, tid);
        wslice(wd, W2vvs, 64, 12, 4, ch * 4, I2f * I3f / 8.f, tid);
        __syncthreads();
        if (!act) continue;
        float acc[16];
#pragma unroll
        for (int k = 0; k < 16; k++) acc[k] = 0.f;
#pragma unroll 1
        for (int i = 0; i < 16; i++) {
            float a = ms[i];
#pragma unroll 2
            for (int j = 0; j < 8; j++)
                fma_k<4>(acc, &ws[(i * 8 + j) * 16], a * es[j]);
        }
#pragma unroll 1
        for (int i = 0; i < 8; i++) {
            float ax = mv[3 * i], ay = mv[3 * i + 1], az = mv[3 * i + 2];
#pragma unroll 2
            for (int j = 0; j < 8; j++) {
                float d = ax * ev[3 * j] + ay * ev[3 * j + 1] + az * ev[3 * j + 2];
                fma_k<4>(acc, &wd[(i * 8 + j) * 16], d);
            }
        }
        if (ch < 2) {
            float* dst = &g_agg[(size_t)c * 80 + ch * 16];
#pragma unroll
            for (int t = 0; t < 16; t++)
                atomicAdd(dst + t, acc[t] * sigm_f(acc[t]));   // silu
        } else {
#pragma unroll
            for (int t = 0; t < 16; t++)
                g_gate[(size_t)t * E + e] = sigm_f(acc[t]);
        }
    }
}

// stage2 vector paths, 2 k-chunks of 8. gate from g_gate, atomic into agg vec slots.
__global__ __launch_bounds__(128, 5) void stage2_v_kernel(
    const float* __restrict__ edge_s, const float* __restrict__ edge_v,
    const int* __restrict__ eidx,
    const float* __restrict__ W2sv, const float* __restrict__ W2vs,
    const float* __restrict__ W2vvv, int E)
{
    __shared__ float wsv[1024], wvs[1024], wvvv[512];
    int tid = threadIdx.x;
    int e = blockIdx.x * 128 + tid;
    bool act = e < E;
    int c = 0;
    float ms[16], mv[24], es[8], ev[24];
    if (act) {
        c = eidx[E + e];
        const float* m = &g_mid[(size_t)e * 40];
#pragma unroll
        for (int q = 0; q < 4; q++) reinterpret_cast<float4*>(ms)[q] = reinterpret_cast<const float4*>(m)[q];
#pragma unroll
        for (int q = 0; q < 6; q++) reinterpret_cast<float4*>(mv)[q] = reinterpret_cast<const float4*>(m)[4 + q];
        ld_f(es, edge_s + (size_t)e * 8, 2);
        ld_f(ev, edge_v + (size_t)e * 24, 6);
    }
#pragma unroll 1
    for (int ch = 0; ch < 2; ch++) {
        __syncthreads();
        wslice(wsv, W2sv, 128, 4, 2, ch * 2, I3f * R128f, tid);
        wslice(wvs, W2vs, 64, 4, 2, ch * 2, I3f / 8.f, tid);
        wslice(wvvv, W2vvv, 64, 4, 2, ch * 2, I2f * I3f / 8.f, tid);
        __syncthreads();
        if (!act) continue;
        float vo[24];
#pragma unroll
        for (int k = 0; k < 24; k++) vo[k] = 0.f;
#pragma unroll 1
        for (int j = 0; j < 8; j++) {
            float A[8];
#pragma unroll
            for (int k = 0; k < 8; k++) A[k] = 0.f;
#pragma unroll 2
            for (int i = 0; i < 16; i++)
                fma_k<2>(A, &wsv[(i * 8 + j) * 8], ms[i]);
            fma_vo8(vo, A, ev[3 * j], ev[3 * j + 1], ev[3 * j + 2]);
        }
#pragma unroll 1
        for (int i = 0; i < 8; i++) {
            float A[8];
#pragma unroll
            for (int k = 0; k < 8; k++) A[k] = 0.f;
#pragma unroll 2
            for (int j = 0; j < 8; j++)
                fma_k<2>(A, &wvs[(i * 8 + j) * 8], es[j]);
            fma_vo8(vo, A, mv[3 * i], mv[3 * i + 1], mv[3 * i + 2]);
        }
#pragma unroll 1
        for (int i = 0; i < 8; i++) {
            float ax = mv[3 * i], ay = mv[3 * i + 1], az = mv[3 * i + 2];
#pragma unroll 1
            for (int j = 0; j < 8; j++) {
                float bx = ev[3 * j], by = ev[3 * j + 1], bz = ev[3 * j + 2];
                fma_cross8(vo, &wvvv[(i * 8 + j) * 8],
                           ay * bz - az * by, az * bx - ax * bz, ax * by - ay * bx);
            }
        }
#pragma unroll
        for (int t = 0; t < 8; t++) {
            float g = g_gate[(size_t)(ch * 8 + t) * E + e];
            float* dst = &g_agg[(size_t)c * 80 + 32 + (ch * 8 + t) * 3];
            atomicAdd(dst + 0, vo[3 * t + 0] * g);
            atomicAdd(dst + 1, vo[3 * t + 1] * g);
            atomicAdd(dst + 2, vo[3 * t + 2] * g);
        }
    }
}

// fold Lms/Lmv into aggregated (post-gate) sums: g_agg[N,80] -> g_agg2[N,40]
__global__ void fold_kernel(const float* __restrict__ Lms, const float* __restrict__ Lmv, int N)
{
    __shared__ float lms[512], lmv[128];
    int tid = threadIdx.x;
    wload(lms, Lms, 128, R32f, tid, 256);
    wload(lmv, Lmv, 32, 0.25f, tid, 256);
    __syncthreads();
    int n = blockIdx.x * 256 + tid;
    if (n >= N) return;
    const float* a = &g_agg[(size_t)n * 80];
    float* o = &g_agg2[(size_t)n * 40];
    float os[16];
#pragma unroll
    for (int k = 0; k < 16; k++) os[k] = 0.f;
#pragma unroll 1
    for (int i = 0; i < 32; i++)
        fma_k<4>(os, &lms[i * 16], a[i]);
#pragma unroll
    for (int k = 0; k < 16; k++) o[k] = os[k];
    float ov[24];
#pragma unroll
    for (int k = 0; k < 24; k++) ov[k] = 0.f;
#pragma unroll 1
    for (int i = 0; i < 16; i++) {
        float ax = a[32 + 3 * i], ay = a[32 + 3 * i + 1], az = a[32 + 3 * i + 2];
        const float* w = &lmv[i * 8];
#pragma unroll
        for (int k = 0; k < 8; k++) {
            float ww = w[k];
            ov[3 * k + 0] += ax * ww; ov[3 * k + 1] += ay * ww; ov[3 * k + 2] += az * ww;
        }
    }
#pragma unroll
    for (int t = 0; t < 24; t++) o[16 + t] = ov[t];
}

// update scalar paths -> g_hid (silu'd for k<32, sigm'd for k>=32)
__global__ __launch_bounds__(128, 5) void update_s_kernel(
    const float* __restrict__ ns, const float* __restrict__ nv,
    const float* __restrict__ W3ss, const float* __restrict__ W3vvs, int N)
{
    __shared__ float ws[4096], wd[1024];
    int tid = threadIdx.x;
    int n = blockIdx.x * 128 + tid;
    bool act = n < N;
    float s1[16], v1[24], s2[16], v2[24];
    if (act) {
        ld_f(s1, ns + (size_t)n * 16, 4);
        ld_f(v1, nv + (size_t)n * 24, 6);
        const float* a = &g_agg2[(size_t)n * 40];
#pragma unroll
        for (int q = 0; q < 4; q++) reinterpret_cast<float4*>(s2)[q] = reinterpret_cast<const float4*>(a)[q];
#pragma unroll
        for (int q = 0; q < 6; q++) reinterpret_cast<float4*>(v2)[q] = reinterpret_cast<const float4*>(a)[4 + q];
    }
#pragma unroll 1
    for (int ch = 0; ch < 3; ch++) {
        __syncthreads();
        wslice(ws, W3ss, 256, 12, 4, ch * 4, I2f / 16.f, tid);
        wslice(wd, W3vvs, 64, 12, 4, ch * 4, I2f * I3f / 8.f, tid);
        __syncthreads();
        if (!act) continue;
        float acc[16];
#pragma unroll
        for (int k = 0; k < 16; k++) acc[k] = 0.f;
#pragma unroll 1
        for (int i = 0; i < 16; i++) {
            float a = s1[i];
#pragma unroll 2
            for (int j = 0; j < 16; j++)
                fma_k<4>(acc, &ws[(i * 16 + j) * 16], a * s2[j]);
        }
#pragma unroll 1
        for (int i = 0; i < 8; i++) {
            float ax = v1[3 * i], ay = v1[3 * i + 1], az = v1[3 * i + 2];
#pragma unroll 2
            for (int j = 0; j < 8; j++) {
                float d = ax * v2[3 * j] + ay * v2[3 * j + 1] + az * v2[3 * j + 2];
                fma_k<4>(acc, &wd[(i * 8 + j) * 16], d);
            }
        }
#pragma unroll
        for (int t = 0; t < 16; t++) {
            float v = (ch < 2) ? acc[t] * sigm_f(acc[t]) : sigm_f(acc[t]);
            g_hid[(size_t)(ch * 16 + t) * N + n] = v;
        }
    }
}

// update vector paths -> gated comps in g_hidv
__global__ __launch_bounds__(128, 5) void update_v_kernel(
    const float* __restrict__ ns, const float* __restrict__ nv,
    const float* __restrict__ W3sv, const float* __restrict__ W3vs,
    const float* __restrict__ W3vvv, int N)
{
    __shared__ float wsv[1024], wvs[1024], wvvv[512];
    int tid = threadIdx.x;
    int n = blockIdx.x * 128 + tid;
    bool act = n < N;
    float s1[16], v1[24], s2[16], v2[24];
    if (act) {
        ld_f(s1, ns + (size_t)n * 16, 4);
        ld_f(v1, nv + (size_t)n * 24, 6);
        const float* a = &g_agg2[(size_t)n * 40];
#pragma unroll
        for (int q = 0; q < 4; q++) reinterpret_cast<float4*>(s2)[q] = reinterpret_cast<const float4*>(a)[q];
#pragma unroll
        for (int q = 0; q < 6; q++) reinterpret_cast<float4*>(v2)[q] = reinterpret_cast<const float4*>(a)[4 + q];
    }
#pragma unroll 1
    for (int ch = 0; ch < 2; ch++) {
        __syncthreads();
        wslice(wsv, W3sv, 128, 4, 2, ch * 2, I3f * R128f, tid);
        wslice(wvs, W3vs, 128, 4, 2, ch * 2, I3f * R128f, tid);
        wslice(wvvv, W3vvv, 64, 4, 2, ch * 2, I2f * I3f / 8.f, tid);
        __syncthreads();
        if (!act) continue;
        float vo[24];
#pragma unroll
        for (int k = 0; k < 24; k++) vo[k] = 0.f;
#pragma unroll 1
        for (int j = 0; j < 8; j++) {
            float A[8];
#pragma unroll
            for (int k = 0; k < 8; k++) A[k] = 0.f;
#pragma unroll 2
            for (int i = 0; i < 16; i++)
                fma_k<2>(A, &wsv[(i * 8 + j) * 8], s1[i]);
            fma_vo8(vo, A, v2[3 * j], v2[3 * j + 1], v2[3 * j + 2]);
        }
#pragma unroll 1
        for (int i = 0; i < 8; i++) {
            float A[8];
#pragma unroll
            for (int k = 0; k < 8; k++) A[k] = 0.f;
#pragma unroll 2
            for (int j = 0; j < 16; j++)
                fma_k<2>(A, &wvs[(i * 16 + j) * 8], s2[j]);
            fma_vo8(vo, A, v1[3 * i], v1[3 * i + 1], v1[3 * i + 2]);
        }
#pragma unroll 1
        for (int i = 0; i < 8; i++) {
            float ax = v1[3 * i], ay = v1[3 * i + 1], az = v1[3 * i + 2];
#pragma unroll 1
            for (int j = 0; j < 8; j++) {
                float bx = v2[3 * j], by = v2[3 * j + 1], bz = v2[3 * j + 2];
                fma_cross8(vo, &wvvv[(i * 8 + j) * 8],
                           ay * bz - az * by, az * bx - ax * bz, ax * by - ay * bx);
            }
        }
#pragma unroll
        for (int t = 0; t < 8; t++) {
            float g = g_hid[(size_t)(32 + ch * 8 + t) * N + n];
#pragma unroll
            for (int cc = 0; cc < 3; cc++)
                g_hidv[(size_t)((ch * 8 + t) * 3 + cc) * N + n] = vo[3 * t + cc] * g;
        }
    }
}

// final: apply Lus/Luv per node, write out[N,40]
__global__ void final_kernel(const float* __restrict__ Lus, const float* __restrict__ Luv,
                             float* __restrict__ out, int N)
{
    __shared__ float lus[512], luv[128];
    int tid = threadIdx.x;
    wload(lus, Lus, 128, R32f, tid, 256);
    wload(luv, Luv, 32, 0.25f, tid, 256);
    __syncthreads();
    int n = blockIdx.x * 256 + tid;
    if (n >= N) return;
    float os[16];
#pragma unroll
    for (int k = 0; k < 16; k++) os[k] = 0.f;
#pragma unroll 1
    for (int i = 0; i < 32; i++)
        fma_k<4>(os, &lus[i * 16], g_hid[(size_t)i * N + n]);
    float ov[24];
#pragma unroll
    for (int k = 0; k < 24; k++) ov[k] = 0.f;
#pragma unroll 1
    for (int i = 0; i < 16; i++) {
        float ax = g_hidv[(size_t)(3 * i + 0) * N + n];
        float ay = g_hidv[(size_t)(3 * i + 1) * N + n];
        float az = g_hidv[(size_t)(3 * i + 2) * N + n];
        const float* w = &luv[i * 8];
#pragma unroll
        for (int k = 0; k < 8; k++) {
            float ww = w[k];
            ov[3 * k + 0] += ax * ww; ov[3 * k + 1] += ay * ww; ov[3 * k + 2] += az * ww;
        }
    }
    float* o = out + (size_t)n * 40;
#pragma unroll
    for (int k = 0; k < 16; k++) o[k] = os[k];
#pragma unroll
    for (int t = 0; t < 24; t++) o[16 + t] = ov[t];
}

// ---------------- launch ----------------
extern "C" void kernel_launch(void* const* d_in, const int* in_sizes, int n_in,
                              void* d_out, int out_size) {
    const float* node_s = (const float*)d_in[0];
    const float* node_v = (const float*)d_in[1];
    const float* edge_s = (const float*)d_in[3];
    const float* edge_v = (const float*)d_in[4];
    const int*   eidx   = (const int*)d_in[5];
    const float* W1ss = (const float*)d_in[6];
    const float* W1sv = (const float*)d_in[7];
    const float* W1vs = (const float*)d_in[8];
    const float* W1vvs = (const float*)d_in[9];
    const float* W1vvv = (const float*)d_in[10];
    const float* W2ss = (const float*)d_in[11];
    const float* W2sv = (const float*)d_in[12];
    const float* W2vs = (const float*)d_in[13];
    const float* W2vvs = (const float*)d_in[14];
    const float* W2vvv = (const float*)d_in[15];
    const float* Lms = (const float*)d_in[16];
    const float* Lmv = (const float*)d_in[17];
    const float* W3ss = (const float*)d_in[18];
    const float* W3sv = (const float*)d_in[19];
    const float* W3vs = (const float*)d_in[20];
    const float* W3vvs = (const float*)d_in[21];
    const float* W3vvv = (const float*)d_in[22];
    const float* Lus = (const float*)d_in[23];
    const float* Luv = (const float*)d_in[24];
    float* out = (float*)d_out;

    int N = in_sizes[0] / 16;
    int E = in_sizes[3] / 8;
    int gE = (E + 127) / 128;
    int gN = (N + 127) / 128;

    zero_kernel<<<(N * 80 + 255) / 256, 256>>>(N * 80);
    stage1_s_kernel<<<gE, 128>>>(node_s, node_v, eidx, W1ss, W1vvs, E);
    stage1_v_kernel<<<gE, 128>>>(node_s, node_v, eidx, W1sv, W1vs, W1vvv, E);
    stage2_s_kernel<<<gE, 128>>>(edge_s, edge_v, eidx, W2ss, W2vvs, E);
    stage2_v_kernel<<<gE, 128>>>(edge_s, edge_v, eidx, W2sv, W2vs, W2vvv, E);
    fold_kernel<<<(N + 255) / 256, 256>>>(Lms, Lmv, N);
    update_s_kernel<<<gN, 128>>>(node_s, node_v, W3ss, W3vvs, N);
    update_v_kernel<<<gN, 128>>>(node_s, node_v, W3sv, W3vs, W3vvv, N);
    final_kernel<<<(N + 255) / 256, 256>>>(Lus, Luv, out, N);
}